// round 14
// baseline (speedup 1.0000x reference)
#include <cuda_runtime.h>
#include <math_constants.h>
#include <cstdint>

// Problem constants (from reference)
#define B_      256
#define N_      16
#define M_      128
#define V_      64
#define H_      256
#define K_      8
#define NP1_    17      // N + 1
#define KO_     136     // K * (N+1)
#define TYPES_  12
#define NCOMBO  180     // 15 spans x 12 types
#define NTHREADS 512

#define CH_ROWS 64                  // H rows per cp.async chunk
#define CH_F    (CH_ROWS * KO_)     // 8704 floats per chunk
#define CH_F4   (CH_F / 4)          // 2176 float4 per chunk
#define DYN_FLOATS (2 * CH_F + H_)  // 17664 floats = 70,656 B

// Output layout: new_d [B,M,V] floats, then new_v [B,40,3,V] zeros
#define OUT_D_ELEMS ((size_t)B_ * M_ * V_)
#define OUT_V_PER_B (40 * 3 * V_)   // 7680 floats per batch

__device__ float g_logits[NCOMBO * KO_];

__device__ __forceinline__ void cp_async16(uint32_t dst, const void* src) {
    asm volatile("cp.async.cg.shared.global [%0], [%1], 16;" :: "r"(dst), "l"(src));
}
__device__ __forceinline__ void cp_commit() {
    asm volatile("cp.async.commit_group;" ::: "memory");
}
template <int N>
__device__ __forceinline__ void cp_wait() {
    asm volatile("cp.async.wait_group %0;" :: "n"(N) : "memory");
}

// ============================================================================
// K1: one block per (span,type) combo — W read exactly once chip-wide.
// cp.async ping-pong stream (R13-proven numerics), writes g_logits.
// ============================================================================
__global__ __launch_bounds__(NTHREADS, 2)
void gemv_combo_kernel(const float* __restrict__ te_table,   // [21,H]
                       const float* __restrict__ W_sem,      // [15,12,H,KO]
                       const float* __restrict__ b_sem)      // [15,12,KO]
{
    extern __shared__ float s_dyn[];
    float* const s_wbuf0 = s_dyn;                 // [CH_F]
    float* const s_wbuf1 = s_dyn + CH_F;          // [CH_F]
    float* const s_te    = s_dyn + 2 * CH_F;      // [H_]
    __shared__ double s_partd[2 * KO_];

    const int combo = blockIdx.x;
    const int tid   = threadIdx.x;
    const int tt    = 9 + combo % TYPES_;

    const float*  __restrict__ Wg  = W_sem + (size_t)combo * H_ * KO_;
    const float4* __restrict__ Wg4 = (const float4*)Wg;

    float bgv = 0.f;
    if (tid < KO_) bgv = __ldg(&b_sem[(size_t)combo * KO_ + tid]);

    const uint32_t a_w0 = (uint32_t)__cvta_generic_to_shared(s_wbuf0);
    const uint32_t a_w1 = (uint32_t)__cvta_generic_to_shared(s_wbuf1);
    const uint32_t a_te = (uint32_t)__cvta_generic_to_shared(s_te);

    // group 0: chunk 0 + te row;  group 1: chunk 1 (register-free MLP)
    for (int i = tid; i < CH_F4; i += NTHREADS)
        cp_async16(a_w0 + i * 16, Wg4 + i);
    if (tid < H_ / 4)
        cp_async16(a_te + tid * 16, (const float4*)(te_table + (size_t)tt * H_) + tid);
    cp_commit();
    for (int i = tid; i < CH_F4; i += NTHREADS)
        cp_async16(a_w1 + i * 16, Wg4 + CH_F4 + i);
    cp_commit();

    // compute mapping: 272 threads = 136 outputs x 2 row-halves of 32
    const int o  = (tid < KO_) ? tid : (tid - KO_);
    const int h0 = (tid < KO_) ? 0 : 32;
    float a[8];
    #pragma unroll
    for (int j = 0; j < 8; j++) a[j] = 0.f;

    #define CHUNK_STEP(c, BUF, WAITN)                                     \
    {                                                                     \
        cp_wait<WAITN>();                                                 \
        __syncthreads();                                                  \
        if (tid < 2 * KO_) {                                              \
            const float* wb = (BUF) + h0 * KO_ + o;                       \
            const float* tp = s_te + (c) * CH_ROWS + h0;                  \
            _Pragma("unroll")                                             \
            for (int j = 0; j < 32; j++)                                  \
                a[j & 7] = fmaf(tp[j], wb[(size_t)j * KO_], a[j & 7]);    \
        }                                                                 \
        __syncthreads();                                                  \
    }

    CHUNK_STEP(0, s_wbuf0, 1)
    for (int i = tid; i < CH_F4; i += NTHREADS)
        cp_async16(a_w0 + i * 16, Wg4 + 2 * CH_F4 + i);
    cp_commit();
    CHUNK_STEP(1, s_wbuf1, 1)
    for (int i = tid; i < CH_F4; i += NTHREADS)
        cp_async16(a_w1 + i * 16, Wg4 + 3 * CH_F4 + i);
    cp_commit();
    CHUNK_STEP(2, s_wbuf0, 1)
    CHUNK_STEP(3, s_wbuf1, 0)
    #undef CHUNK_STEP

    if (tid < 2 * KO_) {
        s_partd[tid] = (((double)a[0] + (double)a[1]) + ((double)a[2] + (double)a[3]))
                     + (((double)a[4] + (double)a[5]) + ((double)a[6] + (double)a[7]));
    }
    __syncthreads();

    if (tid < KO_)
        g_logits[combo * KO_ + tid] =
            (float)(s_partd[tid] + s_partd[tid + KO_]) + bgv;
}

// ============================================================================
// K2 (PDL secondary): preamble overlaps K1; grid-sync; selection + apply.
// ============================================================================
__global__ __launch_bounds__(NTHREADS, 2)
void apply_kernel(const float* __restrict__ decodings,     // [B,N,M,V]
                  const int*   __restrict__ target_types,  // [B]
                  const int*   __restrict__ spans,         // [B]
                  const float* __restrict__ gumbel,        // [B,K,NP1]
                  float*       __restrict__ out)
{
    __shared__ int s_sel[K_];
    __shared__ int s_red[16];
    __shared__ int s_olen;

    const int b    = blockIdx.x;
    const int tid  = threadIdx.x;
    const int w    = tid >> 5;
    const int lane = tid & 31;
    const int tt   = target_types[b];
    const int sp   = spans[b];

    // independent preamble — runs while K1 streams W
    float gval = 0.f;
    if (w < K_ && lane < NP1_)
        gval = __ldg(&gumbel[((size_t)b * K_ + w) * NP1_ + lane]);
    {
        const float4 z = make_float4(0.f, 0.f, 0.f, 0.f);
        float4* __restrict__ dv = (float4*)(out + OUT_D_ELEMS + (size_t)b * OUT_V_PER_B);
        #pragma unroll
        for (int i = tid; i < OUT_V_PER_B / 4; i += NTHREADS)
            dv[i] = z;
    }

    // ---- selection ----
    if (tt == 20) {
        if (tid < K_) s_sel[tid] = (tid == 0) ? 1 : 0;
        __syncthreads();
    } else {
        cudaGridDependencySynchronize();   // wait for K1's g_logits
        if (w < K_) {
            float val = -CUDART_INF_F;
            if (lane < NP1_ && lane <= sp) {
                const int combo = (sp - 2) * TYPES_ + (tt - 9);
                val = g_logits[combo * KO_ + w * NP1_ + lane] + gval;
            }
            float bv = val;
            int   bn = lane;
            #pragma unroll
            for (int off = 16; off; off >>= 1) {
                float ov = __shfl_down_sync(0xffffffffu, bv, off);
                int   on = __shfl_down_sync(0xffffffffu, bn, off);
                if (ov > bv || (ov == bv && on < bn)) { bv = ov; bn = on; }
            }
            if (lane == 0) s_sel[w] = bn;
        }
        __syncthreads();
    }

    // ---- fused speculative copy + olen (R6-proven) ----
    const int c4    = tid & 15;    // float4 column within row (V=64 -> 16 float4)
    const int rbase = tid >> 4;    // base row 0..31
    int idx = 0;

    for (int k = 0; k < K_; k++) {
        if (idx >= M_) break;
        const int n = s_sel[k];
        if (n == 0) continue;

        const float4* __restrict__ tile4 =
            (const float4*)(decodings + ((size_t)b * N_ + (size_t)(n - 1)) * (M_ * V_));
        float4* __restrict__ out4 =
            (float4*)(out + ((size_t)b * M_ + idx) * V_);

        float4 v[4];
        #pragma unroll
        for (int j = 0; j < 4; j++)
            v[j] = tile4[(rbase + 32 * j) * 16 + c4];

        int local = 0;
        #pragma unroll
        for (int j = 0; j < 4; j++) {
            const int row = rbase + 32 * j;
            if (idx + row < M_)
                out4[row * 16 + c4] = v[j];
            // row non-pad iff max over v>0 of d[row][v] > d[row][0]
            float m = (c4 == 0) ? fmaxf(fmaxf(v[j].y, v[j].z), v[j].w)
                                : fmaxf(fmaxf(v[j].x, v[j].y), fmaxf(v[j].z, v[j].w));
            #pragma unroll
            for (int off = 1; off < 16; off <<= 1)
                m = fmaxf(m, __shfl_xor_sync(0xffffffffu, m, off));
            const float d0 = __shfl_sync(0xffffffffu, v[j].x, lane & 16);
            if (m > d0) local = row + 1;
        }
        #pragma unroll
        for (int off = 16; off; off >>= 1)
            local = max(local, __shfl_down_sync(0xffffffffu, local, off));
        if (lane == 0) s_red[w] = local;
        __syncthreads();
        if (tid == 0) {
            int o = 0;
            #pragma unroll
            for (int i = 0; i < 16; i++) o = max(o, s_red[i]);
            s_olen = o;
        }
        __syncthreads();
        idx += min(s_olen, M_ - idx);
    }

    // ---- zero fill tail of new_d ----
    {
        const float4 z = make_float4(0.f, 0.f, 0.f, 0.f);
        float* __restrict__ dst = out + ((size_t)b * M_ + idx) * V_;
        const int rem4 = (M_ - idx) * (V_ / 4);
        for (int i = tid; i < rem4; i += NTHREADS)
            ((float4*)dst)[i] = z;
    }
}

extern "C" void kernel_launch(void* const* d_in, const int* in_sizes, int n_in,
                              void* d_out, int out_size)
{
    (void)in_sizes; (void)n_in; (void)out_size;
    const float* decodings    = (const float*)d_in[0];
    // d_in[1] = variables : unused (new_v is all zeros)
    const int*   target_types = (const int*)d_in[2];
    const int*   spans        = (const int*)d_in[3];
    const float* te_table     = (const float*)d_in[4];
    const float* W_sem        = (const float*)d_in[5];
    const float* b_sem        = (const float*)d_in[6];
    const float* gumbel       = (const float*)d_in[7];
    float*       out          = (float*)d_out;

    const int dyn_bytes = DYN_FLOATS * (int)sizeof(float);   // 70,656 B
    static bool attr_set = false;
    if (!attr_set) {
        cudaFuncSetAttribute(gemv_combo_kernel,
                             cudaFuncAttributeMaxDynamicSharedMemorySize, dyn_bytes);
        attr_set = true;
    }

    // K1: deduped GEMV over all 180 combos
    gemv_combo_kernel<<<NCOMBO, NTHREADS, dyn_bytes>>>(te_table, W_sem, b_sem);

    // K2: PDL secondary — starts during K1, grid-syncs before reading g_logits
    cudaLaunchAttribute attrs[1];
    attrs[0].id = cudaLaunchAttributeProgrammaticStreamSerialization;
    attrs[0].val.programmaticStreamSerializationAllowed = 1;

    cudaLaunchConfig_t cfg = {};
    cfg.gridDim          = dim3(B_);
    cfg.blockDim         = dim3(NTHREADS);
    cfg.dynamicSmemBytes = 0;
    cfg.stream           = 0;
    cfg.attrs            = attrs;
    cfg.numAttrs         = 1;

    cudaError_t e = cudaLaunchKernelEx(&cfg, apply_kernel,
                                       decodings, target_types, spans, gumbel, out);
    if (e != cudaSuccess) {
        // fallback: plain stream-ordered launch (gridDependencySynchronize is
        // a no-op without a pending launch dependency)
        apply_kernel<<<B_, NTHREADS>>>(decodings, target_types, spans, gumbel, out);
    }
}

// round 15
// speedup vs baseline: 1.0043x; 1.0043x over previous
#include <cuda_runtime.h>
#include <math_constants.h>
#include <cstdint>

// Problem constants (from reference)
#define B_      256
#define N_      16
#define M_      128
#define V_      64
#define H_      256
#define K_      8
#define NP1_    17      // N + 1
#define KO_     136     // K * (N+1)
#define TYPES_  12
#define NCOMBO  180     // 15 spans x 12 types
#define NTHREADS 512

#define CH_ROWS 64                  // H rows per cp.async chunk
#define CH_F    (CH_ROWS * KO_)     // 8704 floats per chunk
#define CH_F4   (CH_F / 4)          // 2176 float4 per chunk
#define DYN_FLOATS (2 * CH_F + H_)  // 17664 floats = 70,656 B

// Output layout: new_d [B,M,V] floats, then new_v [B,40,3,V] zeros
#define OUT_D_ELEMS ((size_t)B_ * M_ * V_)
#define OUT_V_PER_B (40 * 3 * V_)   // 7680 floats per batch

__device__ float g_logits[NCOMBO * KO_];

__device__ __forceinline__ void cp_async16(uint32_t dst, const void* src) {
    asm volatile("cp.async.cg.shared.global [%0], [%1], 16;" :: "r"(dst), "l"(src));
}
__device__ __forceinline__ void cp_commit() {
    asm volatile("cp.async.commit_group;" ::: "memory");
}
template <int N>
__device__ __forceinline__ void cp_wait() {
    asm volatile("cp.async.wait_group %0;" :: "n"(N) : "memory");
}

// ============================================================================
// K1: one block per (span,type) combo — W read exactly once chip-wide.
// cp.async ping-pong stream (R13/R14-proven numerics), writes g_logits.
// Triggers PDL at entry so K2's blocks can schedule concurrently.
// ============================================================================
__global__ __launch_bounds__(NTHREADS, 2)
void gemv_combo_kernel(const float* __restrict__ te_table,   // [21,H]
                       const float* __restrict__ W_sem,      // [15,12,H,KO]
                       const float* __restrict__ b_sem)      // [15,12,KO]
{
    // PDL: allow the dependent kernel's blocks to launch NOW. Its
    // cudaGridDependencySynchronize() still waits for this grid's memory,
    // so correctness is unaffected — this only enables overlap.
    cudaTriggerProgrammaticLaunchCompletion();

    extern __shared__ float s_dyn[];
    float* const s_wbuf0 = s_dyn;                 // [CH_F]
    float* const s_wbuf1 = s_dyn + CH_F;          // [CH_F]
    float* const s_te    = s_dyn + 2 * CH_F;      // [H_]
    __shared__ double s_partd[2 * KO_];

    const int combo = blockIdx.x;
    const int tid   = threadIdx.x;
    const int tt    = 9 + combo % TYPES_;

    const float*  __restrict__ Wg  = W_sem + (size_t)combo * H_ * KO_;
    const float4* __restrict__ Wg4 = (const float4*)Wg;

    float bgv = 0.f;
    if (tid < KO_) bgv = __ldg(&b_sem[(size_t)combo * KO_ + tid]);

    const uint32_t a_w0 = (uint32_t)__cvta_generic_to_shared(s_wbuf0);
    const uint32_t a_w1 = (uint32_t)__cvta_generic_to_shared(s_wbuf1);
    const uint32_t a_te = (uint32_t)__cvta_generic_to_shared(s_te);

    // group 0: chunk 0 + te row;  group 1: chunk 1 (register-free MLP)
    for (int i = tid; i < CH_F4; i += NTHREADS)
        cp_async16(a_w0 + i * 16, Wg4 + i);
    if (tid < H_ / 4)
        cp_async16(a_te + tid * 16, (const float4*)(te_table + (size_t)tt * H_) + tid);
    cp_commit();
    for (int i = tid; i < CH_F4; i += NTHREADS)
        cp_async16(a_w1 + i * 16, Wg4 + CH_F4 + i);
    cp_commit();

    // compute mapping: 272 threads = 136 outputs x 2 row-halves of 32
    const int o  = (tid < KO_) ? tid : (tid - KO_);
    const int h0 = (tid < KO_) ? 0 : 32;
    float a[8];
    #pragma unroll
    for (int j = 0; j < 8; j++) a[j] = 0.f;

    #define CHUNK_STEP(c, BUF, WAITN)                                     \
    {                                                                     \
        cp_wait<WAITN>();                                                 \
        __syncthreads();                                                  \
        if (tid < 2 * KO_) {                                              \
            const float* wb = (BUF) + h0 * KO_ + o;                       \
            const float* tp = s_te + (c) * CH_ROWS + h0;                  \
            _Pragma("unroll")                                             \
            for (int j = 0; j < 32; j++)                                  \
                a[j & 7] = fmaf(tp[j], wb[(size_t)j * KO_], a[j & 7]);    \
        }                                                                 \
        __syncthreads();                                                  \
    }

    CHUNK_STEP(0, s_wbuf0, 1)
    for (int i = tid; i < CH_F4; i += NTHREADS)
        cp_async16(a_w0 + i * 16, Wg4 + 2 * CH_F4 + i);
    cp_commit();
    CHUNK_STEP(1, s_wbuf1, 1)
    for (int i = tid; i < CH_F4; i += NTHREADS)
        cp_async16(a_w1 + i * 16, Wg4 + 3 * CH_F4 + i);
    cp_commit();
    CHUNK_STEP(2, s_wbuf0, 1)
    CHUNK_STEP(3, s_wbuf1, 0)
    #undef CHUNK_STEP

    if (tid < 2 * KO_) {
        s_partd[tid] = (((double)a[0] + (double)a[1]) + ((double)a[2] + (double)a[3]))
                     + (((double)a[4] + (double)a[5]) + ((double)a[6] + (double)a[7]));
    }
    __syncthreads();

    if (tid < KO_)
        g_logits[combo * KO_ + tid] =
            (float)(s_partd[tid] + s_partd[tid + KO_]) + bgv;
}

// ============================================================================
// K2 (PDL secondary): preamble overlaps K1; grid-sync; selection + apply.
// ============================================================================
__global__ __launch_bounds__(NTHREADS, 2)
void apply_kernel(const float* __restrict__ decodings,     // [B,N,M,V]
                  const int*   __restrict__ target_types,  // [B]
                  const int*   __restrict__ spans,         // [B]
                  const float* __restrict__ gumbel,        // [B,K,NP1]
                  float*       __restrict__ out)
{
    __shared__ int s_sel[K_];
    __shared__ int s_red[16];
    __shared__ int s_olen;

    const int b    = blockIdx.x;
    const int tid  = threadIdx.x;
    const int w    = tid >> 5;
    const int lane = tid & 31;
    const int tt   = target_types[b];
    const int sp   = spans[b];

    // independent preamble — runs while K1 streams W
    float gval = 0.f;
    if (w < K_ && lane < NP1_)
        gval = __ldg(&gumbel[((size_t)b * K_ + w) * NP1_ + lane]);
    {
        const float4 z = make_float4(0.f, 0.f, 0.f, 0.f);
        float4* __restrict__ dv = (float4*)(out + OUT_D_ELEMS + (size_t)b * OUT_V_PER_B);
        #pragma unroll
        for (int i = tid; i < OUT_V_PER_B / 4; i += NTHREADS)
            dv[i] = z;
    }

    // ---- selection ----
    if (tt == 20) {
        if (tid < K_) s_sel[tid] = (tid == 0) ? 1 : 0;
        __syncthreads();
    } else {
        cudaGridDependencySynchronize();   // wait for K1's g_logits
        if (w < K_) {
            float val = -CUDART_INF_F;
            if (lane < NP1_ && lane <= sp) {
                const int combo = (sp - 2) * TYPES_ + (tt - 9);
                val = g_logits[combo * KO_ + w * NP1_ + lane] + gval;
            }
            float bv = val;
            int   bn = lane;
            #pragma unroll
            for (int off = 16; off; off >>= 1) {
                float ov = __shfl_down_sync(0xffffffffu, bv, off);
                int   on = __shfl_down_sync(0xffffffffu, bn, off);
                if (ov > bv || (ov == bv && on < bn)) { bv = ov; bn = on; }
            }
            if (lane == 0) s_sel[w] = bn;
        }
        __syncthreads();
    }

    // ---- fused speculative copy + olen (R6-proven) ----
    const int c4    = tid & 15;    // float4 column within row (V=64 -> 16 float4)
    const int rbase = tid >> 4;    // base row 0..31
    int idx = 0;

    for (int k = 0; k < K_; k++) {
        if (idx >= M_) break;
        const int n = s_sel[k];
        if (n == 0) continue;

        const float4* __restrict__ tile4 =
            (const float4*)(decodings + ((size_t)b * N_ + (size_t)(n - 1)) * (M_ * V_));
        float4* __restrict__ out4 =
            (float4*)(out + ((size_t)b * M_ + idx) * V_);

        float4 v[4];
        #pragma unroll
        for (int j = 0; j < 4; j++)
            v[j] = tile4[(rbase + 32 * j) * 16 + c4];

        int local = 0;
        #pragma unroll
        for (int j = 0; j < 4; j++) {
            const int row = rbase + 32 * j;
            if (idx + row < M_)
                out4[row * 16 + c4] = v[j];
            // row non-pad iff max over v>0 of d[row][v] > d[row][0]
            float m = (c4 == 0) ? fmaxf(fmaxf(v[j].y, v[j].z), v[j].w)
                                : fmaxf(fmaxf(v[j].x, v[j].y), fmaxf(v[j].z, v[j].w));
            #pragma unroll
            for (int off = 1; off < 16; off <<= 1)
                m = fmaxf(m, __shfl_xor_sync(0xffffffffu, m, off));
            const float d0 = __shfl_sync(0xffffffffu, v[j].x, lane & 16);
            if (m > d0) local = row + 1;
        }
        #pragma unroll
        for (int off = 16; off; off >>= 1)
            local = max(local, __shfl_down_sync(0xffffffffu, local, off));
        if (lane == 0) s_red[w] = local;
        __syncthreads();
        if (tid == 0) {
            int o = 0;
            #pragma unroll
            for (int i = 0; i < 16; i++) o = max(o, s_red[i]);
            s_olen = o;
        }
        __syncthreads();
        idx += min(s_olen, M_ - idx);
    }

    // ---- zero fill tail of new_d ----
    {
        const float4 z = make_float4(0.f, 0.f, 0.f, 0.f);
        float* __restrict__ dst = out + ((size_t)b * M_ + idx) * V_;
        const int rem4 = (M_ - idx) * (V_ / 4);
        for (int i = tid; i < rem4; i += NTHREADS)
            ((float4*)dst)[i] = z;
    }
}

extern "C" void kernel_launch(void* const* d_in, const int* in_sizes, int n_in,
                              void* d_out, int out_size)
{
    (void)in_sizes; (void)n_in; (void)out_size;
    const float* decodings    = (const float*)d_in[0];
    // d_in[1] = variables : unused (new_v is all zeros)
    const int*   target_types = (const int*)d_in[2];
    const int*   spans        = (const int*)d_in[3];
    const float* te_table     = (const float*)d_in[4];
    const float* W_sem        = (const float*)d_in[5];
    const float* b_sem        = (const float*)d_in[6];
    const float* gumbel       = (const float*)d_in[7];
    float*       out          = (float*)d_out;

    const int dyn_bytes = DYN_FLOATS * (int)sizeof(float);   // 70,656 B
    static bool attr_set = false;
    if (!attr_set) {
        cudaFuncSetAttribute(gemv_combo_kernel,
                             cudaFuncAttributeMaxDynamicSharedMemorySize, dyn_bytes);
        attr_set = true;
    }

    // K1: deduped GEMV over all 180 combos (triggers PDL at block entry)
    gemv_combo_kernel<<<NCOMBO, NTHREADS, dyn_bytes>>>(te_table, W_sem, b_sem);

    // K2: PDL secondary — schedules during K1, grid-syncs before g_logits read
    cudaLaunchAttribute attrs[1];
    attrs[0].id = cudaLaunchAttributeProgrammaticStreamSerialization;
    attrs[0].val.programmaticStreamSerializationAllowed = 1;

    cudaLaunchConfig_t cfg = {};
    cfg.gridDim          = dim3(B_);
    cfg.blockDim         = dim3(NTHREADS);
    cfg.dynamicSmemBytes = 0;
    cfg.stream           = 0;
    cfg.attrs            = attrs;
    cfg.numAttrs         = 1;

    cudaError_t e = cudaLaunchKernelEx(&cfg, apply_kernel,
                                       decodings, target_types, spans, gumbel, out);
    if (e != cudaSuccess) {
        // fallback: plain stream-ordered launch (gridDependencySynchronize is
        // a no-op without a pending launch dependency)
        apply_kernel<<<B_, NTHREADS>>>(decodings, target_types, spans, gumbel, out);
    }
}